// round 1
// baseline (speedup 1.0000x reference)
#include <cuda_runtime.h>
#include <cuda_fp16.h>

#define DDIM  256
#define NMAX  8192

// Scratch: normalized y rows in fp16 (4 MB, L2-resident) + row norms (fp32).
__device__ __half2 g_yn[(size_t)NMAX * (DDIM / 2)];
__device__ float   g_ynorm[NMAX];

__device__ __forceinline__ float warp_sum(float v) {
#pragma unroll
    for (int off = 16; off; off >>= 1)
        v += __shfl_xor_sync(0xffffffffu, v, off);
    return v;
}

// One warp per y row: compute norm, store fp16 normalized copy + norm scalar.
__global__ void __launch_bounds__(256) prep_y(const float* __restrict__ y, int M) {
    int w    = (blockIdx.x * blockDim.x + threadIdx.x) >> 5;
    int lane = threadIdx.x & 31;
    if (w >= M) return;

    const float4* yp = (const float4*)(y + (size_t)w * DDIM);
    float4 a = yp[lane * 2];
    float4 b = yp[lane * 2 + 1];
    float ss = a.x * a.x + a.y * a.y + a.z * a.z + a.w * a.w
             + b.x * b.x + b.y * b.y + b.z * b.z + b.w * b.w;
    ss = warp_sum(ss);
    float n   = fmaxf(sqrtf(ss), 1e-8f);   // matches max(norm, EPS)
    float inv = 1.0f / n;
    if (lane == 0) g_ynorm[w] = n;

    __half2* o = g_yn + (size_t)w * (DDIM / 2) + lane * 4;
    o[0] = __floats2half2_rn(a.x * inv, a.y * inv);
    o[1] = __floats2half2_rn(a.z * inv, a.w * inv);
    o[2] = __floats2half2_rn(b.x * inv, b.y * inv);
    o[3] = __floats2half2_rn(b.z * inv, b.w * inv);
}

// One warp per output row. Scan adj (streaming), ballot nonzeros, process each
// neighbor warp-cooperatively: fp16 dot (cosine), fixed-shift softmax weight,
// fp32 accumulate of P@y via reconstructed y = yn * ynorm.
__global__ void __launch_bounds__(256) gat_main(const float* __restrict__ x,
                                               const float* __restrict__ adj,
                                               float* __restrict__ out,
                                               int N, int M) {
    int warp = (blockIdx.x * blockDim.x + threadIdx.x) >> 5;
    int lane = threadIdx.x & 31;
    if (warp >= N) return;
    const int i = warp;

    // Load x row (this lane owns dims [8*lane, 8*lane+8)), normalize.
    const float4* xp = (const float4*)(x + (size_t)i * DDIM);
    float4 xa = xp[lane * 2];
    float4 xb = xp[lane * 2 + 1];
    float ss = xa.x * xa.x + xa.y * xa.y + xa.z * xa.z + xa.w * xa.w
             + xb.x * xb.x + xb.y * xb.y + xb.z * xb.z + xb.w * xb.w;
    ss = warp_sum(ss);
    float xinv = 1.0f / fmaxf(sqrtf(ss), 1e-8f);

    __half2 xh0 = __floats2half2_rn(xa.x * xinv, xa.y * xinv);
    __half2 xh1 = __floats2half2_rn(xa.z * xinv, xa.w * xinv);
    __half2 xh2 = __floats2half2_rn(xb.x * xinv, xb.y * xinv);
    __half2 xh3 = __floats2half2_rn(xb.z * xinv, xb.w * xinv);

    float o0 = 0.f, o1 = 0.f, o2 = 0.f, o3 = 0.f;
    float o4 = 0.f, o5 = 0.f, o6 = 0.f, o7 = 0.f;
    float l = 0.f;

    const float* arow = adj + (size_t)i * M;

    for (int j0 = 0; j0 < M; j0 += 128) {
        // Streaming load: don't let adj evict the L2-resident yn table.
        float4 a = __ldcs((const float4*)(arow + j0 + lane * 4));
        unsigned m0 = __ballot_sync(0xffffffffu, a.x != 0.f);
        unsigned m1 = __ballot_sync(0xffffffffu, a.y != 0.f);
        unsigned m2 = __ballot_sync(0xffffffffu, a.z != 0.f);
        unsigned m3 = __ballot_sync(0xffffffffu, a.w != 0.f);

#pragma unroll
        for (int t = 0; t < 4; ++t) {
            unsigned mm = (t == 0) ? m0 : (t == 1) ? m1 : (t == 2) ? m2 : m3;
            while (mm) {
                int b = __ffs(mm) - 1;
                mm &= mm - 1;
                int j = j0 + 4 * b + t;

                const uint4 v = *(const uint4*)(g_yn + (size_t)j * (DDIM / 2) + lane * 4);
                __half2 y0 = *(const __half2*)&v.x;
                __half2 y1 = *(const __half2*)&v.y;
                __half2 y2 = *(const __half2*)&v.z;
                __half2 y3 = *(const __half2*)&v.w;

                // cosine = xn . yn  (fp16 pairwise, fp32 cross-lane)
                __half2 acc = __hmul2(xh0, y0);
                acc = __hfma2(xh1, y1, acc);
                acc = __hfma2(xh2, y2, acc);
                acc = __hfma2(xh3, y3, acc);
                float2 af = __half22float2(acc);
                float d = warp_sum(af.x + af.y);

                // fixed-shift softmax weight (cos <= 1 always; matches ref ratios)
                float p = __expf(d - 1.0f);
                l += p;
                float q = p * __ldg(&g_ynorm[j]);   // fold in y reconstruction

                float2 f0 = __half22float2(y0);
                float2 f1 = __half22float2(y1);
                float2 f2 = __half22float2(y2);
                float2 f3 = __half22float2(y3);
                o0 = fmaf(q, f0.x, o0);
                o1 = fmaf(q, f0.y, o1);
                o2 = fmaf(q, f1.x, o2);
                o3 = fmaf(q, f1.y, o3);
                o4 = fmaf(q, f2.x, o4);
                o5 = fmaf(q, f2.y, o5);
                o6 = fmaf(q, f3.x, o6);
                o7 = fmaf(q, f3.y, o7);
            }
        }
    }

    float s = 0.5f / l;   // l > 0 guaranteed (diagonal entry in adj)
    float4 r0, r1;
    r0.x = fmaf(s, o0, 0.5f * xa.x);
    r0.y = fmaf(s, o1, 0.5f * xa.y);
    r0.z = fmaf(s, o2, 0.5f * xa.z);
    r0.w = fmaf(s, o3, 0.5f * xa.w);
    r1.x = fmaf(s, o4, 0.5f * xb.x);
    r1.y = fmaf(s, o5, 0.5f * xb.y);
    r1.z = fmaf(s, o6, 0.5f * xb.z);
    r1.w = fmaf(s, o7, 0.5f * xb.w);

    float4* op = (float4*)(out + (size_t)i * DDIM);
    op[lane * 2]     = r0;
    op[lane * 2 + 1] = r1;
}

extern "C" void kernel_launch(void* const* d_in, const int* in_sizes, int n_in,
                              void* d_out, int out_size) {
    const float* x   = (const float*)d_in[0];
    const float* y   = (const float*)d_in[1];
    const float* adj = (const float*)d_in[2];
    float* out       = (float*)d_out;

    int N = in_sizes[0] / DDIM;   // 8192
    int M = in_sizes[1] / DDIM;   // 8192

    int prep_blocks = (M * 32 + 255) / 256;
    prep_y<<<prep_blocks, 256>>>(y, M);

    int main_blocks = (N * 32 + 255) / 256;
    gat_main<<<main_blocks, 256>>>(x, adj, out, N, M);
}

// round 3
// speedup vs baseline: 1.0495x; 1.0495x over previous
#include <cuda_runtime.h>
#include <cuda_fp16.h>

#define DDIM  256
#define NMAX  8192
#define LISTCAP 640          // binomial(8192, 0.02) mean ~164, sd ~12.7 -> 640 is ~37 sigma
#define BATCH 8

// Scratch: normalized y rows in fp16 (4 MB, L2-resident) + row norms (fp32).
__device__ __half2 g_yn[(size_t)NMAX * (DDIM / 2)];
__device__ float   g_ynorm[NMAX];

__device__ __forceinline__ float warp_sum(float v) {
#pragma unroll
    for (int off = 16; off; off >>= 1)
        v += __shfl_xor_sync(0xffffffffu, v, off);
    return v;
}

// One warp per y row: compute norm, store fp16 normalized copy + norm scalar.
__global__ void __launch_bounds__(256) prep_y(const float* __restrict__ y, int M) {
    int w    = (blockIdx.x * blockDim.x + threadIdx.x) >> 5;
    int lane = threadIdx.x & 31;
    if (w >= M) return;

    const float4* yp = (const float4*)(y + (size_t)w * DDIM);
    float4 a = yp[lane * 2];
    float4 b = yp[lane * 2 + 1];
    float ss = a.x * a.x + a.y * a.y + a.z * a.z + a.w * a.w
             + b.x * b.x + b.y * b.y + b.z * b.z + b.w * b.w;
    ss = warp_sum(ss);
    float n   = fmaxf(sqrtf(ss), 1e-8f);   // matches max(norm, EPS)
    float inv = 1.0f / n;
    if (lane == 0) g_ynorm[w] = n;

    __half2* o = g_yn + (size_t)w * (DDIM / 2) + lane * 4;
    o[0] = __floats2half2_rn(a.x * inv, a.y * inv);
    o[1] = __floats2half2_rn(a.z * inv, a.w * inv);
    o[2] = __floats2half2_rn(b.x * inv, b.y * inv);
    o[3] = __floats2half2_rn(b.z * inv, b.w * inv);
}

// One warp per output row, two phases:
//  A) scan adj row, compact nonzero column indices into a smem list
//  B) process neighbors in batches of BATCH: 8 outstanding L2 loads,
//     8 independent fp16 dots, 8 interleaved butterfly reductions (ILP hides
//     the 5-step SHFL dependency of each).
__global__ void __launch_bounds__(256) gat_main(const float* __restrict__ x,
                                               const float* __restrict__ adj,
                                               float* __restrict__ out,
                                               int N, int M) {
    __shared__ unsigned short s_list[8][LISTCAP];

    int warp = (blockIdx.x * blockDim.x + threadIdx.x) >> 5;
    int wib  = (threadIdx.x >> 5);
    int lane = threadIdx.x & 31;
    if (warp >= N) return;
    const int i = warp;
    unsigned short* lst = s_list[wib];

    // ---- Load + normalize x row (lane owns dims [8*lane, 8*lane+8)) ----
    const float4* xp = (const float4*)(x + (size_t)i * DDIM);
    float4 xa = xp[lane * 2];
    float4 xb = xp[lane * 2 + 1];
    float ss = xa.x * xa.x + xa.y * xa.y + xa.z * xa.z + xa.w * xa.w
             + xb.x * xb.x + xb.y * xb.y + xb.z * xb.z + xb.w * xb.w;
    ss = warp_sum(ss);
    float xinv = 1.0f / fmaxf(sqrtf(ss), 1e-8f);

    __half2 xh0 = __floats2half2_rn(xa.x * xinv, xa.y * xinv);
    __half2 xh1 = __floats2half2_rn(xa.z * xinv, xa.w * xinv);
    __half2 xh2 = __floats2half2_rn(xb.x * xinv, xb.y * xinv);
    __half2 xh3 = __floats2half2_rn(xb.z * xinv, xb.w * xinv);

    // ---- Phase A: compact adjacency row into index list ----
    const float* arow = adj + (size_t)i * M;
    const unsigned lt = (1u << lane) - 1u;
    int cnt = 0;

    for (int j0 = 0; j0 < M; j0 += 128) {
        float4 a = __ldcs((const float4*)(arow + j0 + lane * 4));
        unsigned m0 = __ballot_sync(0xffffffffu, a.x != 0.f);
        unsigned m1 = __ballot_sync(0xffffffffu, a.y != 0.f);
        unsigned m2 = __ballot_sync(0xffffffffu, a.z != 0.f);
        unsigned m3 = __ballot_sync(0xffffffffu, a.w != 0.f);
        int c0 = __popc(m0), c1 = __popc(m1), c2 = __popc(m2), c3 = __popc(m3);
        int jb = j0 + 4 * lane;
        if (a.x != 0.f) lst[cnt + __popc(m0 & lt)]                = (unsigned short)(jb);
        if (a.y != 0.f) lst[cnt + c0 + __popc(m1 & lt)]           = (unsigned short)(jb + 1);
        if (a.z != 0.f) lst[cnt + c0 + c1 + __popc(m2 & lt)]      = (unsigned short)(jb + 2);
        if (a.w != 0.f) lst[cnt + c0 + c1 + c2 + __popc(m3 & lt)] = (unsigned short)(jb + 3);
        cnt += c0 + c1 + c2 + c3;
    }
    __syncwarp();

    // ---- Phase B: batched neighbor processing ----
    float o0 = 0.f, o1 = 0.f, o2 = 0.f, o3 = 0.f;
    float o4 = 0.f, o5 = 0.f, o6 = 0.f, o7 = 0.f;
    float l = 0.f;

    for (int base = 0; base < cnt; base += BATCH) {
        int   jj[BATCH];
        uint4 v[BATCH];
        float d[BATCH];

        // 8 outstanding 16B L2 loads
#pragma unroll
        for (int k = 0; k < BATCH; ++k) {
            int idx = base + k;
            jj[k] = lst[idx < cnt ? idx : 0];
            v[k] = *(const uint4*)(g_yn + (size_t)jj[k] * (DDIM / 2) + lane * 4);
        }

        // 8 independent partial dots
#pragma unroll
        for (int k = 0; k < BATCH; ++k) {
            __half2 acc = __hmul2(xh0, *(const __half2*)&v[k].x);
            acc = __hfma2(xh1, *(const __half2*)&v[k].y, acc);
            acc = __hfma2(xh2, *(const __half2*)&v[k].z, acc);
            acc = __hfma2(xh3, *(const __half2*)&v[k].w, acc);
            float2 af = __half22float2(acc);
            d[k] = af.x + af.y;
        }

        // 8 interleaved butterfly reductions: each step issues 8 independent
        // SHFLs, so the 5-step dependent chain is pipelined across the batch.
#pragma unroll
        for (int off = 16; off; off >>= 1) {
#pragma unroll
            for (int k = 0; k < BATCH; ++k)
                d[k] += __shfl_xor_sync(0xffffffffu, d[k], off);
        }

        // softmax weights (fixed shift: cos <= 1) + P@y accumulation
#pragma unroll
        for (int k = 0; k < BATCH; ++k) {
            float p = (base + k < cnt) ? __expf(d[k] - 1.0f) : 0.f;
            l += p;
            float q = p * __ldg(&g_ynorm[jj[k]]);   // fold in y reconstruction
            float2 f0 = __half22float2(*(const __half2*)&v[k].x);
            float2 f1 = __half22float2(*(const __half2*)&v[k].y);
            float2 f2 = __half22float2(*(const __half2*)&v[k].z);
            float2 f3 = __half22float2(*(const __half2*)&v[k].w);
            o0 = fmaf(q, f0.x, o0);
            o1 = fmaf(q, f0.y, o1);
            o2 = fmaf(q, f1.x, o2);
            o3 = fmaf(q, f1.y, o3);
            o4 = fmaf(q, f2.x, o4);
            o5 = fmaf(q, f2.y, o5);
            o6 = fmaf(q, f3.x, o6);
            o7 = fmaf(q, f3.y, o7);
        }
    }

    float s = 0.5f / l;   // l > 0 guaranteed (diagonal entry in adj)
    float4 r0, r1;
    r0.x = fmaf(s, o0, 0.5f * xa.x);
    r0.y = fmaf(s, o1, 0.5f * xa.y);
    r0.z = fmaf(s, o2, 0.5f * xa.z);
    r0.w = fmaf(s, o3, 0.5f * xa.w);
    r1.x = fmaf(s, o4, 0.5f * xb.x);
    r1.y = fmaf(s, o5, 0.5f * xb.y);
    r1.z = fmaf(s, o6, 0.5f * xb.z);
    r1.w = fmaf(s, o7, 0.5f * xb.w);

    float4* op = (float4*)(out + (size_t)i * DDIM);
    op[lane * 2]     = r0;
    op[lane * 2 + 1] = r1;
}

extern "C" void kernel_launch(void* const* d_in, const int* in_sizes, int n_in,
                              void* d_out, int out_size) {
    const float* x   = (const float*)d_in[0];
    const float* y   = (const float*)d_in[1];
    const float* adj = (const float*)d_in[2];
    float* out       = (float*)d_out;

    int N = in_sizes[0] / DDIM;   // 8192
    int M = in_sizes[1] / DDIM;   // 8192

    int prep_blocks = (M * 32 + 255) / 256;
    prep_y<<<prep_blocks, 256>>>(y, M);

    int main_blocks = (N * 32 + 255) / 256;
    gat_main<<<main_blocks, 256>>>(x, adj, out, N, M);
}

// round 4
// speedup vs baseline: 1.4218x; 1.3548x over previous
#include <cuda_runtime.h>
#include <cuda_fp16.h>

#define DDIM  256
#define NMAX  8192
#define LISTCAP 640          // binomial(8192, 0.02) mean ~164, sd ~12.7 -> 640 is ~37 sigma
#define BATCH 8

// Scratch: normalized y rows in fp16 (4 MB, L2-resident) + row norms (fp32).
__device__ __half2 g_yn[(size_t)NMAX * (DDIM / 2)];
__device__ float   g_ynorm[NMAX];

__device__ __forceinline__ float warp_sum(float v) {
#pragma unroll
    for (int off = 16; off; off >>= 1)
        v += __shfl_xor_sync(0xffffffffu, v, off);
    return v;
}

// One warp per y row: compute norm, store fp16 normalized copy + norm scalar.
__global__ void __launch_bounds__(256) prep_y(const float* __restrict__ y, int M) {
    int w    = (blockIdx.x * blockDim.x + threadIdx.x) >> 5;
    int lane = threadIdx.x & 31;
    if (w >= M) return;

    const float4* yp = (const float4*)(y + (size_t)w * DDIM);
    float4 a = yp[lane * 2];
    float4 b = yp[lane * 2 + 1];
    float ss = a.x * a.x + a.y * a.y + a.z * a.z + a.w * a.w
             + b.x * b.x + b.y * b.y + b.z * b.z + b.w * b.w;
    ss = warp_sum(ss);
    float n   = fmaxf(sqrtf(ss), 1e-8f);   // matches max(norm, EPS)
    float inv = 1.0f / n;
    if (lane == 0) g_ynorm[w] = n;

    __half2* o = g_yn + (size_t)w * (DDIM / 2) + lane * 4;
    o[0] = __floats2half2_rn(a.x * inv, a.y * inv);
    o[1] = __floats2half2_rn(a.z * inv, a.w * inv);
    o[2] = __floats2half2_rn(b.x * inv, b.y * inv);
    o[3] = __floats2half2_rn(b.z * inv, b.w * inv);
}

// One warp per output row, two phases:
//  A) scan adj row with 4 loads in flight (MLP=4 on the DRAM stream),
//     compact nonzero column indices into a smem list
//  B) process neighbors in batches of BATCH with all loads live
//     (launch_bounds reg budget), packed 9-SHFL multi-reduction.
__global__ void __launch_bounds__(256, 1) gat_main(const float* __restrict__ x,
                                                   const float* __restrict__ adj,
                                                   float* __restrict__ out,
                                                   int N, int M) {
    __shared__ unsigned short s_list[8][LISTCAP];

    int warp = (blockIdx.x * blockDim.x + threadIdx.x) >> 5;
    int wib  = (threadIdx.x >> 5);
    int lane = threadIdx.x & 31;
    if (warp >= N) return;
    const int i = warp;
    unsigned short* lst = s_list[wib];

    // ---- Load + normalize x row (lane owns dims [8*lane, 8*lane+8)) ----
    const float4* xp = (const float4*)(x + (size_t)i * DDIM);
    float4 xa = xp[lane * 2];
    float4 xb = xp[lane * 2 + 1];
    float ss = xa.x * xa.x + xa.y * xa.y + xa.z * xa.z + xa.w * xa.w
             + xb.x * xb.x + xb.y * xb.y + xb.z * xb.z + xb.w * xb.w;
    ss = warp_sum(ss);
    float xinv = 1.0f / fmaxf(sqrtf(ss), 1e-8f);

    __half2 xh0 = __floats2half2_rn(xa.x * xinv, xa.y * xinv);
    __half2 xh1 = __floats2half2_rn(xa.z * xinv, xa.w * xinv);
    __half2 xh2 = __floats2half2_rn(xb.x * xinv, xb.y * xinv);
    __half2 xh3 = __floats2half2_rn(xb.z * xinv, xb.w * xinv);

    // ---- Phase A: compact adjacency row, 4 loads in flight ----
    const float* arow = adj + (size_t)i * M;
    const unsigned lt = (1u << lane) - 1u;
    int cnt = 0;

    int j0 = 0;
    for (; j0 + 512 <= M; j0 += 512) {
        float4 a0 = __ldcs((const float4*)(arow + j0 +   0 + lane * 4));
        float4 a1 = __ldcs((const float4*)(arow + j0 + 128 + lane * 4));
        float4 a2 = __ldcs((const float4*)(arow + j0 + 256 + lane * 4));
        float4 a3 = __ldcs((const float4*)(arow + j0 + 384 + lane * 4));
#pragma unroll
        for (int u = 0; u < 4; ++u) {
            float4 a = (u == 0) ? a0 : (u == 1) ? a1 : (u == 2) ? a2 : a3;
            int jb = j0 + 128 * u + 4 * lane;
            unsigned m0 = __ballot_sync(0xffffffffu, a.x != 0.f);
            unsigned m1 = __ballot_sync(0xffffffffu, a.y != 0.f);
            unsigned m2 = __ballot_sync(0xffffffffu, a.z != 0.f);
            unsigned m3 = __ballot_sync(0xffffffffu, a.w != 0.f);
            int c0 = __popc(m0), c1 = __popc(m1), c2 = __popc(m2), c3 = __popc(m3);
            if (a.x != 0.f) lst[cnt + __popc(m0 & lt)]                = (unsigned short)(jb);
            if (a.y != 0.f) lst[cnt + c0 + __popc(m1 & lt)]           = (unsigned short)(jb + 1);
            if (a.z != 0.f) lst[cnt + c0 + c1 + __popc(m2 & lt)]      = (unsigned short)(jb + 2);
            if (a.w != 0.f) lst[cnt + c0 + c1 + c2 + __popc(m3 & lt)] = (unsigned short)(jb + 3);
            cnt += c0 + c1 + c2 + c3;
        }
    }
    for (; j0 < M; j0 += 128) {   // generic tail (unused for M=8192)
        float4 a = __ldcs((const float4*)(arow + j0 + lane * 4));
        int jb = j0 + 4 * lane;
        unsigned m0 = __ballot_sync(0xffffffffu, a.x != 0.f);
        unsigned m1 = __ballot_sync(0xffffffffu, a.y != 0.f);
        unsigned m2 = __ballot_sync(0xffffffffu, a.z != 0.f);
        unsigned m3 = __ballot_sync(0xffffffffu, a.w != 0.f);
        int c0 = __popc(m0), c1 = __popc(m1), c2 = __popc(m2), c3 = __popc(m3);
        if (a.x != 0.f) lst[cnt + __popc(m0 & lt)]                = (unsigned short)(jb);
        if (a.y != 0.f) lst[cnt + c0 + __popc(m1 & lt)]           = (unsigned short)(jb + 1);
        if (a.z != 0.f) lst[cnt + c0 + c1 + __popc(m2 & lt)]      = (unsigned short)(jb + 2);
        if (a.w != 0.f) lst[cnt + c0 + c1 + c2 + __popc(m3 & lt)] = (unsigned short)(jb + 3);
        cnt += c0 + c1 + c2 + c3;
    }
    __syncwarp();

    // ---- Phase B: batched neighbor processing ----
    float o0 = 0.f, o1 = 0.f, o2 = 0.f, o3 = 0.f;
    float o4 = 0.f, o5 = 0.f, o6 = 0.f, o7 = 0.f;
    float l = 0.f;

    const bool lo16 = (lane & 16) == 0;
    const bool lo8  = (lane & 8)  == 0;
    const bool lo4  = (lane & 4)  == 0;

    for (int base = 0; base < cnt; base += BATCH) {
        int   jj[BATCH];
        uint4 v[BATCH];
        float d[BATCH];

        // 8 outstanding 16B L2 loads
#pragma unroll
        for (int k = 0; k < BATCH; ++k) {
            int idx = base + k;
            jj[k] = lst[idx < cnt ? idx : 0];
            v[k] = *(const uint4*)(g_yn + (size_t)jj[k] * (DDIM / 2) + lane * 4);
        }

        // uniform ynorm prefetch (overlaps with reduction below)
        float yn[BATCH];
#pragma unroll
        for (int k = 0; k < BATCH; ++k)
            yn[k] = __ldg(&g_ynorm[jj[k]]);

        // 8 independent partial dots
#pragma unroll
        for (int k = 0; k < BATCH; ++k) {
            __half2 acc = __hmul2(xh0, *(const __half2*)&v[k].x);
            acc = __hfma2(xh1, *(const __half2*)&v[k].y, acc);
            acc = __hfma2(xh2, *(const __half2*)&v[k].z, acc);
            acc = __hfma2(xh3, *(const __half2*)&v[k].w, acc);
            float2 af = __half22float2(acc);
            d[k] = af.x + af.y;
        }

        // Packed multi-value reduction: 8 values -> 9 SHFLs total.
        // Level 1 (offset 16): lanes<16 keep values 0..3, lanes>=16 keep 4..7.
#pragma unroll
        for (int k = 0; k < 4; ++k) {
            float send = lo16 ? d[k + 4] : d[k];
            float recv = __shfl_xor_sync(0xffffffffu, send, 16);
            d[k] = (lo16 ? d[k] : d[k + 4]) + recv;
        }
        // Level 2 (offset 8): keep 2 values.
#pragma unroll
        for (int k = 0; k < 2; ++k) {
            float send = lo8 ? d[k + 2] : d[k];
            float recv = __shfl_xor_sync(0xffffffffu, send, 8);
            d[k] = (lo8 ? d[k] : d[k + 2]) + recv;
        }
        // Level 3 (offset 4): keep 1 value.
        {
            float send = lo4 ? d[1] : d[0];
            float recv = __shfl_xor_sync(0xffffffffu, send, 4);
            d[0] = (lo4 ? d[0] : d[1]) + recv;
        }
        // Finish within 4-lane group (offsets 2, 1).
        d[0] += __shfl_xor_sync(0xffffffffu, d[0], 2);
        d[0] += __shfl_xor_sync(0xffffffffu, d[0], 1);

        // One exp per lane; value k's total lives in lane 4k (and its group).
        float e = __expf(d[0] - 1.0f);

        // Broadcast the 8 totals, mask padding, fold in ynorm, accumulate.
#pragma unroll
        for (int k = 0; k < BATCH; ++k) {
            float ek = __shfl_sync(0xffffffffu, e, 4 * k);
            float p  = (base + k < cnt) ? ek : 0.f;
            l += p;
            float q = p * yn[k];
            float2 f0 = __half22float2(*(const __half2*)&v[k].x);
            float2 f1 = __half22float2(*(const __half2*)&v[k].y);
            float2 f2 = __half22float2(*(const __half2*)&v[k].z);
            float2 f3 = __half22float2(*(const __half2*)&v[k].w);
            o0 = fmaf(q, f0.x, o0);
            o1 = fmaf(q, f0.y, o1);
            o2 = fmaf(q, f1.x, o2);
            o3 = fmaf(q, f1.y, o3);
            o4 = fmaf(q, f2.x, o4);
            o5 = fmaf(q, f2.y, o5);
            o6 = fmaf(q, f3.x, o6);
            o7 = fmaf(q, f3.y, o7);
        }
    }

    float s = 0.5f / l;   // l > 0 guaranteed (diagonal entry in adj)
    float4 r0, r1;
    r0.x = fmaf(s, o0, 0.5f * xa.x);
    r0.y = fmaf(s, o1, 0.5f * xa.y);
    r0.z = fmaf(s, o2, 0.5f * xa.z);
    r0.w = fmaf(s, o3, 0.5f * xa.w);
    r1.x = fmaf(s, o4, 0.5f * xb.x);
    r1.y = fmaf(s, o5, 0.5f * xb.y);
    r1.z = fmaf(s, o6, 0.5f * xb.z);
    r1.w = fmaf(s, o7, 0.5f * xb.w);

    float4* op = (float4*)(out + (size_t)i * DDIM);
    op[lane * 2]     = r0;
    op[lane * 2 + 1] = r1;
}

extern "C" void kernel_launch(void* const* d_in, const int* in_sizes, int n_in,
                              void* d_out, int out_size) {
    const float* x   = (const float*)d_in[0];
    const float* y   = (const float*)d_in[1];
    const float* adj = (const float*)d_in[2];
    float* out       = (float*)d_out;

    int N = in_sizes[0] / DDIM;   // 8192
    int M = in_sizes[1] / DDIM;   // 8192

    int prep_blocks = (M * 32 + 255) / 256;
    prep_y<<<prep_blocks, 256>>>(y, M);

    int main_blocks = (N * 32 + 255) / 256;
    gat_main<<<main_blocks, 256>>>(x, adj, out, N, M);
}